// round 8
// baseline (speedup 1.0000x reference)
#include <cuda_runtime.h>
#include <cuda_fp16.h>
#include <cstdint>

// Problem constants
#define Tt    1024
#define Bb    8
#define Ee    1024
#define Hh    16
#define Dh    64
#define QKVF  3072           // 3*E
#define MROWS 8192           // T*B

// Scratch (device globals — no runtime allocation allowed)
__device__ __half g_xh  [(size_t)MROWS * Ee];    // query, fp16
__device__ __half g_w1h [(size_t)QKVF * Ee];     // qkv_w, fp16
__device__ __half g_w2h [(size_t)Ee * Ee];       // out_w, fp16
__device__ __half g_qkvh[(size_t)MROWS * QKVF];  // qkv proj out (Q pre-scaled), fp16
__device__ __half g_atth[(size_t)MROWS * Ee];    // attention out, fp16

// ---------------------------------------------------------------------------
// Helpers
// ---------------------------------------------------------------------------
__device__ __forceinline__ uint32_t packh2(float lo, float hi) {
    __half2 h = __floats2half2_rn(lo, hi);
    return *reinterpret_cast<uint32_t*>(&h);
}

__device__ __forceinline__ void mma16(float* c,
                                      uint32_t a0, uint32_t a1, uint32_t a2, uint32_t a3,
                                      uint32_t b0, uint32_t b1) {
    asm volatile("mma.sync.aligned.m16n8k16.row.col.f32.f16.f16.f32 "
                 "{%0,%1,%2,%3}, {%4,%5,%6,%7}, {%8,%9}, {%0,%1,%2,%3};"
                 : "+f"(c[0]), "+f"(c[1]), "+f"(c[2]), "+f"(c[3])
                 : "r"(a0), "r"(a1), "r"(a2), "r"(a3), "r"(b0), "r"(b1));
}

__device__ __forceinline__ void ldsm4(uint32_t& r0, uint32_t& r1, uint32_t& r2, uint32_t& r3,
                                      uint32_t addr) {
    asm volatile("ldmatrix.sync.aligned.m8n8.x4.shared.b16 {%0,%1,%2,%3}, [%4];"
                 : "=r"(r0), "=r"(r1), "=r"(r2), "=r"(r3) : "r"(addr));
}

__device__ __forceinline__ void ldsm4t(uint32_t& r0, uint32_t& r1, uint32_t& r2, uint32_t& r3,
                                       uint32_t addr) {
    asm volatile("ldmatrix.sync.aligned.m8n8.x4.trans.shared.b16 {%0,%1,%2,%3}, [%4];"
                 : "=r"(r0), "=r"(r1), "=r"(r2), "=r"(r3) : "r"(addr));
}

// ---------------------------------------------------------------------------
// Prepass: fp32 -> fp16 (RN)
// ---------------------------------------------------------------------------
__global__ void cvt_f32_f16(const float4* __restrict__ in, uint2* __restrict__ out, int n4) {
    int i = blockIdx.x * blockDim.x + threadIdx.x;
    if (i < n4) {
        float4 v = in[i];
        uint2 o;
        o.x = packh2(v.x, v.y);
        o.y = packh2(v.z, v.w);
        out[i] = o;
    }
}

// ---------------------------------------------------------------------------
// fp16 tensor-core GEMM (NT): C[M,N] = A[M,K]*B[N,K]^T, epilogue (acc+bias)*scale
// CTA tile 128x128, 4 warps (2m x 2n), warp tile 64x64.
// Pipeline: 3 pair-buffers of k64 (2 x k32 chunks, 16KB each) = 96KB smem,
// ONE wait_group+syncthreads per k64 -> halved barrier frequency.
// Buffer reuse safety: pair-buffer (cp+2)%3 was consumed at iter cp-1; its
// readers precede the barrier at iter cp, after which we overwrite it.
// ---------------------------------------------------------------------------
#define BM   128
#define BN   128
#define BKH  32
#define ABY  (BM * 64)          // 8192
#define BBY  (BN * 64)          // 8192
#define STG  (ABY + BBY)        // 16384 per k32 chunk
#define PAIRB (2 * STG)         // 32768 per k64 pair
#define GSM  (3 * PAIRB)        // 98304

__global__ void __launch_bounds__(128, 2) gemm_f16(
    const __half* __restrict__ Ah, const __half* __restrict__ Bh,
    const float* __restrict__ bias, __half* __restrict__ Ch, float* __restrict__ Cf,
    int M, int N, int K, int qscale)
{
    extern __shared__ char smem[];
    const uint32_t sb = (uint32_t)__cvta_generic_to_shared(smem);
    const int tid  = threadIdx.x;
    const int lane = tid & 31;
    const int warp = tid >> 5;
    const int wm = warp & 1;
    const int wn = warp >> 1;
    const int m0 = blockIdx.y * BM;
    const int n0 = blockIdx.x * BN;

    float acc[4][8][4];
    #pragma unroll
    for (int mt = 0; mt < 4; mt++)
        #pragma unroll
        for (int nt = 0; nt < 8; nt++)
            #pragma unroll
            for (int i = 0; i < 4; i++) acc[mt][nt][i] = 0.0f;

    // Load one k64 pair (chunks c, c+1) into pair-buffer p; one commit group.
    auto load_pair = [&](int p, int c) {
        #pragma unroll
        for (int half = 0; half < 2; half++) {
            const uint32_t base = sb + p * PAIRB + half * STG;
            const int k0 = (c + half) * BKH;
            #pragma unroll
            for (int i = 0; i < 8; i++) {
                int q = tid + i * 128;
                uint32_t dst;
                const __half* src;
                if (q < 512) {                   // A: 128 rows x 4 chunks
                    int r = q >> 2, ch = q & 3;
                    src = Ah + (size_t)(m0 + r) * K + k0 + ch * 8;
                    dst = base + r * 64 + ((ch ^ ((r >> 1) & 3)) << 4);
                } else {                         // B: 128 rows x 4 chunks
                    int q2 = q - 512;
                    int r = q2 >> 2, ch = q2 & 3;
                    src = Bh + (size_t)(n0 + r) * K + k0 + ch * 8;
                    dst = base + ABY + r * 64 + ((ch ^ ((r >> 1) & 3)) << 4);
                }
                asm volatile("cp.async.cg.shared.global [%0], [%1], 16;" :: "r"(dst), "l"(src));
            }
        }
        asm volatile("cp.async.commit_group;" ::: "memory");
    };

    const int nk = K / BKH;        // k32 chunks
    const int npair = nk >> 1;     // k64 pairs

    load_pair(0, 0);
    load_pair(1, 2);

    const int a_rl = ((lane >> 3) & 1) * 8 + (lane & 7);
    const int a_ck = lane >> 4;
    const int b_rl = ((lane >> 4) & 1) * 8 + (lane & 7);
    const int b_ck = (lane >> 3) & 1;

    // Hoisted fragment byte offsets within a k32 chunk (per ks-half, per tile)
    uint32_t aoff[2][4], boff[2][4];
    #pragma unroll
    for (int ks = 0; ks < 2; ks++) {
        #pragma unroll
        for (int mt = 0; mt < 4; mt++) {
            int ar = wm * 64 + mt * 16 + a_rl;
            int ch = (2 * ks + a_ck) ^ ((ar >> 1) & 3);
            aoff[ks][mt] = ar * 64 + (ch << 4);
        }
        #pragma unroll
        for (int p = 0; p < 4; p++) {
            int br = wn * 64 + p * 16 + b_rl;
            int ch = (2 * ks + b_ck) ^ ((br >> 1) & 3);
            boff[ks][p] = ABY + br * 64 + (ch << 4);
        }
    }

    int pbuf = 0;                 // pair-buffer index = cp % 3
    for (int cp = 0; cp < npair; cp++) {
        if (cp < npair - 1) asm volatile("cp.async.wait_group 1;" ::: "memory");
        else                asm volatile("cp.async.wait_group 0;" ::: "memory");
        __syncthreads();

        // Prefetch into the buffer consumed at iter cp-1 (safe past the barrier)
        if (cp + 2 < npair) {
            int p2 = pbuf + 2; if (p2 >= 3) p2 -= 3;
            load_pair(p2, 2 * (cp + 2));
        }

        const uint32_t pbase = sb + pbuf * PAIRB;
        #pragma unroll
        for (int half = 0; half < 2; half++) {
            const uint32_t base = pbase + half * STG;
            #pragma unroll
            for (int ks = 0; ks < 2; ks++) {
                uint32_t af[4][4], bf[8][2];
                #pragma unroll
                for (int mt = 0; mt < 4; mt++)
                    ldsm4(af[mt][0], af[mt][1], af[mt][2], af[mt][3], base + aoff[ks][mt]);
                #pragma unroll
                for (int p = 0; p < 4; p++) {
                    uint32_t r0, r1, r2, r3;
                    ldsm4(r0, r1, r2, r3, base + boff[ks][p]);
                    bf[2 * p][0] = r0;     bf[2 * p][1] = r1;
                    bf[2 * p + 1][0] = r2; bf[2 * p + 1][1] = r3;
                }
                #pragma unroll
                for (int mt = 0; mt < 4; mt++)
                    #pragma unroll
                    for (int nt = 0; nt < 8; nt++)
                        mma16(acc[mt][nt], af[mt][0], af[mt][1], af[mt][2], af[mt][3],
                              bf[nt][0], bf[nt][1]);
            }
        }
        if (++pbuf == 3) pbuf = 0;
    }

    // Epilogue
    const float scale = (qscale && n0 < Ee) ? 0.125f : 1.0f;
    const int g = lane >> 2, t = lane & 3;
    #pragma unroll
    for (int mt = 0; mt < 4; mt++) {
        const int r0 = m0 + wm * 64 + mt * 16 + g;
        #pragma unroll
        for (int nt = 0; nt < 8; nt++) {
            const int col = n0 + wn * 64 + nt * 8 + 2 * t;
            const float b0 = bias[col], b1 = bias[col + 1];
            float v00 = (acc[mt][nt][0] + b0) * scale;
            float v01 = (acc[mt][nt][1] + b1) * scale;
            float v10 = (acc[mt][nt][2] + b0) * scale;
            float v11 = (acc[mt][nt][3] + b1) * scale;
            if (Ch) {
                *(uint32_t*)&Ch[(size_t)r0 * N + col]       = packh2(v00, v01);
                *(uint32_t*)&Ch[(size_t)(r0 + 8) * N + col] = packh2(v10, v11);
            } else {
                *(float2*)&Cf[(size_t)r0 * N + col]       = make_float2(v00, v01);
                *(float2*)&Cf[(size_t)(r0 + 8) * N + col] = make_float2(v10, v11);
            }
        }
    }
}

// ---------------------------------------------------------------------------
// Flash attention, fp16 tensor cores, causal. qt reversed so heavy (long)
// causal blocks launch first -> better tail balance.
// ---------------------------------------------------------------------------
#define FST 16384   // per-stage bytes: K 8KB + V 8KB

__global__ void __launch_bounds__(128) flash_f16()
{
    __shared__ __align__(128) char fsm[2 * FST];
    const uint32_t sb = (uint32_t)__cvta_generic_to_shared(fsm);

    const int tid  = threadIdx.x;
    const int lane = tid & 31;
    const int g    = lane >> 2;
    const int t    = lane & 3;
    const int w    = tid >> 5;
    const int qt   = gridDim.x - 1 - blockIdx.x;   // heavy tiles first
    const int bh   = blockIdx.y;
    const int b    = bh >> 4;
    const int h    = bh & 15;
    const int q0   = qt * 64;

    // Q fragments (Q already scaled by 0.125 in GEMM1 epilogue)
    uint32_t qa[4][4];
    {
        const __half* qlo = g_qkvh + ((size_t)(q0 + w * 16 + g) * Bb + b) * QKVF + h * Dh;
        const __half* qhi = qlo + (size_t)8 * Bb * QKVF;
        #pragma unroll
        for (int ks = 0; ks < 4; ks++) {
            qa[ks][0] = *(const uint32_t*)(qlo + ks * 16 + 2 * t);
            qa[ks][1] = *(const uint32_t*)(qhi + ks * 16 + 2 * t);
            qa[ks][2] = *(const uint32_t*)(qlo + ks * 16 + 8 + 2 * t);
            qa[ks][3] = *(const uint32_t*)(qhi + ks * 16 + 8 + 2 * t);
        }
    }

    auto load_kv = [&](int st, int kt) {
        const uint32_t base = sb + st * FST;
        const int k0 = kt * 64;
        #pragma unroll
        for (int i = 0; i < 8; i++) {
            int q = tid + i * 128;
            int off, s, c;
            uint32_t dstb;
            if (q < 512) { s = q >> 3; c = q & 7; off = Ee;     dstb = base; }
            else { int q2 = q - 512; s = q2 >> 3; c = q2 & 7; off = 2 * Ee; dstb = base + 8192; }
            const __half* src = g_qkvh + ((size_t)(k0 + s) * Bb + b) * QKVF + off + h * Dh + c * 8;
            uint32_t dst = dstb + s * 128 + ((c ^ (s & 7)) << 4);
            asm volatile("cp.async.cg.shared.global [%0], [%1], 16;" :: "r"(dst), "l"(src));
        }
        asm volatile("cp.async.commit_group;" ::: "memory");
    };

    load_kv(0, 0);

    float o[8][4];
    #pragma unroll
    for (int nt = 0; nt < 8; nt++)
        #pragma unroll
        for (int i = 0; i < 4; i++) o[nt][i] = 0.0f;
    float m0v = -1e30f, m1v = -1e30f, l0 = 0.0f, l1 = 0.0f;

    const int krl = ((lane >> 4) & 1) * 8 + (lane & 7);
    const int kck = (lane >> 3) & 1;
    const int vrl = ((lane >> 3) & 1) * 8 + (lane & 7);
    const int vck = lane >> 4;

    for (int kt = 0; kt <= qt; kt++) {
        asm volatile("cp.async.wait_group 0;" ::: "memory");
        __syncthreads();
        if (kt < qt) load_kv((kt + 1) & 1, kt + 1);

        const uint32_t Kb = sb + (kt & 1) * FST;
        const uint32_t Vb = Kb + 8192;

        // S = Q K^T
        float sv[8][4];
        #pragma unroll
        for (int nt = 0; nt < 8; nt++)
            #pragma unroll
            for (int i = 0; i < 4; i++) sv[nt][i] = 0.0f;

        #pragma unroll
        for (int ks = 0; ks < 4; ks++) {
            #pragma unroll
            for (int p = 0; p < 4; p++) {
                int n = p * 16 + krl;
                int ch = (2 * ks + kck) ^ (n & 7);
                uint32_t r0, r1, r2, r3;
                ldsm4(r0, r1, r2, r3, Kb + n * 128 + (ch << 4));
                mma16(sv[2 * p],     qa[ks][0], qa[ks][1], qa[ks][2], qa[ks][3], r0, r1);
                mma16(sv[2 * p + 1], qa[ks][0], qa[ks][1], qa[ks][2], qa[ks][3], r2, r3);
            }
        }

        // Causal mask (diagonal tile only)
        if (kt == qt) {
            const int r_lo = w * 16 + g, r_hi = r_lo + 8;
            #pragma unroll
            for (int nt = 0; nt < 8; nt++) {
                const int c0 = nt * 8 + 2 * t, c1 = c0 + 1;
                if (c0 > r_lo) sv[nt][0] = -1e30f;
                if (c1 > r_lo) sv[nt][1] = -1e30f;
                if (c0 > r_hi) sv[nt][2] = -1e30f;
                if (c1 > r_hi) sv[nt][3] = -1e30f;
            }
        }

        // Online softmax
        float mx0 = -1e30f, mx1 = -1e30f;
        #pragma unroll
        for (int nt = 0; nt < 8; nt++) {
            mx0 = fmaxf(mx0, fmaxf(sv[nt][0], sv[nt][1]));
            mx1 = fmaxf(mx1, fmaxf(sv[nt][2], sv[nt][3]));
        }
        mx0 = fmaxf(mx0, __shfl_xor_sync(0xffffffffu, mx0, 1));
        mx0 = fmaxf(mx0, __shfl_xor_sync(0xffffffffu, mx0, 2));
        mx1 = fmaxf(mx1, __shfl_xor_sync(0xffffffffu, mx1, 1));
        mx1 = fmaxf(mx1, __shfl_xor_sync(0xffffffffu, mx1, 2));

        const float mn0 = fmaxf(m0v, mx0), mn1 = fmaxf(m1v, mx1);
        const float al0 = __expf(m0v - mn0), al1 = __expf(m1v - mn1);
        m0v = mn0; m1v = mn1;

        float sum0 = 0.0f, sum1 = 0.0f;
        #pragma unroll
        for (int nt = 0; nt < 8; nt++) {
            sv[nt][0] = __expf(sv[nt][0] - mn0); sum0 += sv[nt][0];
            sv[nt][1] = __expf(sv[nt][1] - mn0); sum0 += sv[nt][1];
            sv[nt][2] = __expf(sv[nt][2] - mn1); sum1 += sv[nt][2];
            sv[nt][3] = __expf(sv[nt][3] - mn1); sum1 += sv[nt][3];
        }
        sum0 += __shfl_xor_sync(0xffffffffu, sum0, 1);
        sum0 += __shfl_xor_sync(0xffffffffu, sum0, 2);
        sum1 += __shfl_xor_sync(0xffffffffu, sum1, 1);
        sum1 += __shfl_xor_sync(0xffffffffu, sum1, 2);
        l0 = l0 * al0 + sum0;
        l1 = l1 * al1 + sum1;

        #pragma unroll
        for (int nt = 0; nt < 8; nt++) {
            o[nt][0] *= al0; o[nt][1] *= al0;
            o[nt][2] *= al1; o[nt][3] *= al1;
        }

        // O += P V  (P register-resident, packed to fp16)
        #pragma unroll
        for (int ks = 0; ks < 4; ks++) {
            const uint32_t p0 = packh2(sv[2 * ks][0],     sv[2 * ks][1]);
            const uint32_t p1 = packh2(sv[2 * ks][2],     sv[2 * ks][3]);
            const uint32_t p2 = packh2(sv[2 * ks + 1][0], sv[2 * ks + 1][1]);
            const uint32_t p3 = packh2(sv[2 * ks + 1][2], sv[2 * ks + 1][3]);
            #pragma unroll
            for (int p = 0; p < 4; p++) {
                int srow = ks * 16 + vrl;
                int ch = (2 * p + vck) ^ (srow & 7);
                uint32_t r0, r1, r2, r3;
                ldsm4t(r0, r1, r2, r3, Vb + srow * 128 + (ch << 4));
                mma16(o[2 * p],     p0, p1, p2, p3, r0, r1);
                mma16(o[2 * p + 1], p0, p1, p2, p3, r2, r3);
            }
        }
    }

    // Epilogue: normalize, write fp16 [T,B,E]
    const float inv0 = 1.0f / l0, inv1 = 1.0f / l1;
    __half* dlo = g_atth + ((size_t)(q0 + w * 16 + g) * Bb + b) * Ee + h * Dh;
    __half* dhi = dlo + (size_t)8 * Bb * Ee;
    #pragma unroll
    for (int nt = 0; nt < 8; nt++) {
        const int c = nt * 8 + 2 * t;
        *(uint32_t*)&dlo[c] = packh2(o[nt][0] * inv0, o[nt][1] * inv0);
        *(uint32_t*)&dhi[c] = packh2(o[nt][2] * inv1, o[nt][3] * inv1);
    }
}

// ---------------------------------------------------------------------------
// Launch
// ---------------------------------------------------------------------------
extern "C" void kernel_launch(void* const* d_in, const int* in_sizes, int n_in,
                              void* d_out, int out_size)
{
    const float* query = (const float*)d_in[0];
    const float* qkv_w = (const float*)d_in[1];
    const float* qkv_b = (const float*)d_in[2];
    const float* out_w = (const float*)d_in[3];
    const float* out_b = (const float*)d_in[4];
    float* out = (float*)d_out;

    void *p_xh = nullptr, *p_w1h = nullptr, *p_w2h = nullptr,
         *p_qkvh = nullptr, *p_atth = nullptr;
    cudaGetSymbolAddress(&p_xh,   g_xh);
    cudaGetSymbolAddress(&p_w1h,  g_w1h);
    cudaGetSymbolAddress(&p_w2h,  g_w2h);
    cudaGetSymbolAddress(&p_qkvh, g_qkvh);
    cudaGetSymbolAddress(&p_atth, g_atth);

    cudaFuncSetAttribute(gemm_f16, cudaFuncAttributeMaxDynamicSharedMemorySize, GSM);

    // 0) fp32 -> fp16 prepass
    cvt_f32_f16<<<(MROWS * Ee / 4 + 255) / 256, 256>>>((const float4*)query, (uint2*)p_xh,  MROWS * Ee / 4);
    cvt_f32_f16<<<(QKVF  * Ee / 4 + 255) / 256, 256>>>((const float4*)qkv_w, (uint2*)p_w1h, QKVF  * Ee / 4);
    cvt_f32_f16<<<(Ee    * Ee / 4 + 255) / 256, 256>>>((const float4*)out_w, (uint2*)p_w2h, Ee    * Ee / 4);

    // 1) QKV projection -> fp16, Q block scaled by 0.125
    gemm_f16<<<dim3(QKVF / BN, MROWS / BM), 128, GSM>>>(
        (const __half*)p_xh, (const __half*)p_w1h, qkv_b,
        (__half*)p_qkvh, nullptr, MROWS, QKVF, Ee, 1);

    // 2) Causal flash attention per (query-tile, b*H+h)
    flash_f16<<<dim3(Tt / 64, Bb * Hh), 128>>>();

    // 3) Output projection -> fp32 final output
    gemm_f16<<<dim3(Ee / BN, MROWS / BM), 128, GSM>>>(
        (const __half*)p_atth, (const __half*)p_w2h, out_b,
        nullptr, out, MROWS, Ee, Ee, 0);
}

// round 9
// speedup vs baseline: 1.0779x; 1.0779x over previous
#include <cuda_runtime.h>
#include <cuda_fp16.h>
#include <cstdint>

// Problem constants
#define Tt    1024
#define Bb    8
#define Ee    1024
#define Hh    16
#define Dh    64
#define QKVF  3072           // 3*E
#define MROWS 8192           // T*B

// Scratch (device globals — no runtime allocation allowed)
__device__ __half g_xh  [(size_t)MROWS * Ee];    // query, fp16
__device__ __half g_w1h [(size_t)QKVF * Ee];     // qkv_w, fp16
__device__ __half g_w2h [(size_t)Ee * Ee];       // out_w, fp16
__device__ __half g_qkvh[(size_t)MROWS * QKVF];  // qkv proj out (Q pre-scaled), fp16
__device__ __half g_atth[(size_t)MROWS * Ee];    // attention out, fp16

// ---------------------------------------------------------------------------
// Helpers
// ---------------------------------------------------------------------------
__device__ __forceinline__ uint32_t packh2(float lo, float hi) {
    __half2 h = __floats2half2_rn(lo, hi);
    return *reinterpret_cast<uint32_t*>(&h);
}

__device__ __forceinline__ void mma16(float* c,
                                      uint32_t a0, uint32_t a1, uint32_t a2, uint32_t a3,
                                      uint32_t b0, uint32_t b1) {
    asm volatile("mma.sync.aligned.m16n8k16.row.col.f32.f16.f16.f32 "
                 "{%0,%1,%2,%3}, {%4,%5,%6,%7}, {%8,%9}, {%0,%1,%2,%3};"
                 : "+f"(c[0]), "+f"(c[1]), "+f"(c[2]), "+f"(c[3])
                 : "r"(a0), "r"(a1), "r"(a2), "r"(a3), "r"(b0), "r"(b1));
}

__device__ __forceinline__ void ldsm4(uint32_t& r0, uint32_t& r1, uint32_t& r2, uint32_t& r3,
                                      uint32_t addr) {
    asm volatile("ldmatrix.sync.aligned.m8n8.x4.shared.b16 {%0,%1,%2,%3}, [%4];"
                 : "=r"(r0), "=r"(r1), "=r"(r2), "=r"(r3) : "r"(addr));
}

__device__ __forceinline__ void ldsm4t(uint32_t& r0, uint32_t& r1, uint32_t& r2, uint32_t& r3,
                                       uint32_t addr) {
    asm volatile("ldmatrix.sync.aligned.m8n8.x4.trans.shared.b16 {%0,%1,%2,%3}, [%4];"
                 : "=r"(r0), "=r"(r1), "=r"(r2), "=r"(r3) : "r"(addr));
}

// ---------------------------------------------------------------------------
// Prepass: fp32 -> fp16 (RN)
// ---------------------------------------------------------------------------
__global__ void cvt_f32_f16(const float4* __restrict__ in, uint2* __restrict__ out, int n4) {
    int i = blockIdx.x * blockDim.x + threadIdx.x;
    if (i < n4) {
        float4 v = in[i];
        uint2 o;
        o.x = packh2(v.x, v.y);
        o.y = packh2(v.z, v.w);
        out[i] = o;
    }
}

// ---------------------------------------------------------------------------
// fp16 tensor-core GEMM (NT): C[M,N] = A[M,K]*B[N,K]^T, epilogue (acc+bias)*scale
// CTA tile 128x128, 4 warps (2m x 2n), warp tile 64x64, BK=32 halfs.
// 5-stage cp.async pipeline (80KB smem -> 2 CTAs/SM); prefetch for chunk c+3
// is issued BEFORE the wait/barrier into stage (c+3)%5 = (c-2)%5, which was
// consumed at iter c-2 (all warps passed barrier c-1, so no reader remains).
// ---------------------------------------------------------------------------
#define BM   128
#define BN   128
#define BKH  32
#define NSG  5
#define ABY  (BM * 64)          // 8192
#define BBY  (BN * 64)          // 8192
#define STG  (ABY + BBY)        // 16384 per k32 stage
#define GSM  (NSG * STG)        // 81920

__global__ void __launch_bounds__(128, 2) gemm_f16(
    const __half* __restrict__ Ah, const __half* __restrict__ Bh,
    const float* __restrict__ bias, __half* __restrict__ Ch, float* __restrict__ Cf,
    int M, int N, int K, int qscale)
{
    extern __shared__ char smem[];
    const uint32_t sb = (uint32_t)__cvta_generic_to_shared(smem);
    const int tid  = threadIdx.x;
    const int lane = tid & 31;
    const int warp = tid >> 5;
    const int wm = warp & 1;
    const int wn = warp >> 1;
    const int m0 = blockIdx.y * BM;
    const int n0 = blockIdx.x * BN;

    float acc[4][8][4];
    #pragma unroll
    for (int mt = 0; mt < 4; mt++)
        #pragma unroll
        for (int nt = 0; nt < 8; nt++)
            #pragma unroll
            for (int i = 0; i < 4; i++) acc[mt][nt][i] = 0.0f;

    auto load_stage = [&](int s, int c) {
        const uint32_t base = sb + s * STG;
        const int k0 = c * BKH;
        #pragma unroll
        for (int i = 0; i < 8; i++) {
            int q = tid + i * 128;
            uint32_t dst;
            const __half* src;
            if (q < 512) {                   // A: 128 rows x 4 chunks
                int r = q >> 2, ch = q & 3;
                src = Ah + (size_t)(m0 + r) * K + k0 + ch * 8;
                dst = base + r * 64 + ((ch ^ ((r >> 1) & 3)) << 4);
            } else {                         // B: 128 rows x 4 chunks
                int q2 = q - 512;
                int r = q2 >> 2, ch = q2 & 3;
                src = Bh + (size_t)(n0 + r) * K + k0 + ch * 8;
                dst = base + ABY + r * 64 + ((ch ^ ((r >> 1) & 3)) << 4);
            }
            asm volatile("cp.async.cg.shared.global [%0], [%1], 16;" :: "r"(dst), "l"(src));
        }
        asm volatile("cp.async.commit_group;" ::: "memory");
    };

    const int nk = K / BKH;
    load_stage(0, 0);
    load_stage(1, 1);
    load_stage(2, 2);

    const int a_rl = ((lane >> 3) & 1) * 8 + (lane & 7);
    const int a_ck = lane >> 4;
    const int b_rl = ((lane >> 4) & 1) * 8 + (lane & 7);
    const int b_ck = (lane >> 3) & 1;

    // Hoisted fragment byte offsets within a stage (per ks-half, per tile)
    uint32_t aoff[2][4], boff[2][4];
    #pragma unroll
    for (int ks = 0; ks < 2; ks++) {
        #pragma unroll
        for (int mt = 0; mt < 4; mt++) {
            int ar = wm * 64 + mt * 16 + a_rl;
            int ch = (2 * ks + a_ck) ^ ((ar >> 1) & 3);
            aoff[ks][mt] = ar * 64 + (ch << 4);
        }
        #pragma unroll
        for (int p = 0; p < 4; p++) {
            int br = wn * 64 + p * 16 + b_rl;
            int ch = (2 * ks + b_ck) ^ ((br >> 1) & 3);
            boff[ks][p] = ABY + br * 64 + (ch << 4);
        }
    }

    int sbuf = 0;   // stage index = c % 5
    int pbuf = 3;   // prefetch stage index = (c+3) % 5
    for (int c = 0; c < nk; c++) {
        // Prefetch BEFORE the wait: chunk c+3 into stage (c+3)%5 = (c-2)%5,
        // consumed at iter c-2; all warps passed barrier c-1 -> safe.
        if (c + 3 < nk) load_stage(pbuf, c + 3);

        if (c + 4 <= nk) asm volatile("cp.async.wait_group 3;" ::: "memory");
        else             asm volatile("cp.async.wait_group 0;" ::: "memory");
        __syncthreads();

        const uint32_t base = sb + sbuf * STG;
        #pragma unroll
        for (int ks = 0; ks < 2; ks++) {
            uint32_t af[4][4], bf[8][2];
            #pragma unroll
            for (int mt = 0; mt < 4; mt++)
                ldsm4(af[mt][0], af[mt][1], af[mt][2], af[mt][3], base + aoff[ks][mt]);
            #pragma unroll
            for (int p = 0; p < 4; p++) {
                uint32_t r0, r1, r2, r3;
                ldsm4(r0, r1, r2, r3, base + boff[ks][p]);
                bf[2 * p][0] = r0;     bf[2 * p][1] = r1;
                bf[2 * p + 1][0] = r2; bf[2 * p + 1][1] = r3;
            }
            #pragma unroll
            for (int mt = 0; mt < 4; mt++)
                #pragma unroll
                for (int nt = 0; nt < 8; nt++)
                    mma16(acc[mt][nt], af[mt][0], af[mt][1], af[mt][2], af[mt][3],
                          bf[nt][0], bf[nt][1]);
        }
        if (++sbuf == NSG) sbuf = 0;
        if (++pbuf == NSG) pbuf = 0;
    }

    // Epilogue
    const float scale = (qscale && n0 < Ee) ? 0.125f : 1.0f;
    const int g = lane >> 2, t = lane & 3;
    #pragma unroll
    for (int mt = 0; mt < 4; mt++) {
        const int r0 = m0 + wm * 64 + mt * 16 + g;
        #pragma unroll
        for (int nt = 0; nt < 8; nt++) {
            const int col = n0 + wn * 64 + nt * 8 + 2 * t;
            const float b0 = bias[col], b1 = bias[col + 1];
            float v00 = (acc[mt][nt][0] + b0) * scale;
            float v01 = (acc[mt][nt][1] + b1) * scale;
            float v10 = (acc[mt][nt][2] + b0) * scale;
            float v11 = (acc[mt][nt][3] + b1) * scale;
            if (Ch) {
                *(uint32_t*)&Ch[(size_t)r0 * N + col]       = packh2(v00, v01);
                *(uint32_t*)&Ch[(size_t)(r0 + 8) * N + col] = packh2(v10, v11);
            } else {
                *(float2*)&Cf[(size_t)r0 * N + col]       = make_float2(v00, v01);
                *(float2*)&Cf[(size_t)(r0 + 8) * N + col] = make_float2(v10, v11);
            }
        }
    }
}

// ---------------------------------------------------------------------------
// Flash attention, fp16 tensor cores, causal. qt reversed (heavy tiles first).
// ---------------------------------------------------------------------------
#define FST 16384   // per-stage bytes: K 8KB + V 8KB

__global__ void __launch_bounds__(128) flash_f16()
{
    __shared__ __align__(128) char fsm[2 * FST];
    const uint32_t sb = (uint32_t)__cvta_generic_to_shared(fsm);

    const int tid  = threadIdx.x;
    const int lane = tid & 31;
    const int g    = lane >> 2;
    const int t    = lane & 3;
    const int w    = tid >> 5;
    const int qt   = gridDim.x - 1 - blockIdx.x;   // heavy tiles first
    const int bh   = blockIdx.y;
    const int b    = bh >> 4;
    const int h    = bh & 15;
    const int q0   = qt * 64;

    // Q fragments (Q already scaled by 0.125 in GEMM1 epilogue)
    uint32_t qa[4][4];
    {
        const __half* qlo = g_qkvh + ((size_t)(q0 + w * 16 + g) * Bb + b) * QKVF + h * Dh;
        const __half* qhi = qlo + (size_t)8 * Bb * QKVF;
        #pragma unroll
        for (int ks = 0; ks < 4; ks++) {
            qa[ks][0] = *(const uint32_t*)(qlo + ks * 16 + 2 * t);
            qa[ks][1] = *(const uint32_t*)(qhi + ks * 16 + 2 * t);
            qa[ks][2] = *(const uint32_t*)(qlo + ks * 16 + 8 + 2 * t);
            qa[ks][3] = *(const uint32_t*)(qhi + ks * 16 + 8 + 2 * t);
        }
    }

    auto load_kv = [&](int st, int kt) {
        const uint32_t base = sb + st * FST;
        const int k0 = kt * 64;
        #pragma unroll
        for (int i = 0; i < 8; i++) {
            int q = tid + i * 128;
            int off, s, c;
            uint32_t dstb;
            if (q < 512) { s = q >> 3; c = q & 7; off = Ee;     dstb = base; }
            else { int q2 = q - 512; s = q2 >> 3; c = q2 & 7; off = 2 * Ee; dstb = base + 8192; }
            const __half* src = g_qkvh + ((size_t)(k0 + s) * Bb + b) * QKVF + off + h * Dh + c * 8;
            uint32_t dst = dstb + s * 128 + ((c ^ (s & 7)) << 4);
            asm volatile("cp.async.cg.shared.global [%0], [%1], 16;" :: "r"(dst), "l"(src));
        }
        asm volatile("cp.async.commit_group;" ::: "memory");
    };

    load_kv(0, 0);

    float o[8][4];
    #pragma unroll
    for (int nt = 0; nt < 8; nt++)
        #pragma unroll
        for (int i = 0; i < 4; i++) o[nt][i] = 0.0f;
    float m0v = -1e30f, m1v = -1e30f, l0 = 0.0f, l1 = 0.0f;

    const int krl = ((lane >> 4) & 1) * 8 + (lane & 7);
    const int kck = (lane >> 3) & 1;
    const int vrl = ((lane >> 3) & 1) * 8 + (lane & 7);
    const int vck = lane >> 4;

    for (int kt = 0; kt <= qt; kt++) {
        asm volatile("cp.async.wait_group 0;" ::: "memory");
        __syncthreads();
        if (kt < qt) load_kv((kt + 1) & 1, kt + 1);

        const uint32_t Kb = sb + (kt & 1) * FST;
        const uint32_t Vb = Kb + 8192;

        // S = Q K^T
        float sv[8][4];
        #pragma unroll
        for (int nt = 0; nt < 8; nt++)
            #pragma unroll
            for (int i = 0; i < 4; i++) sv[nt][i] = 0.0f;

        #pragma unroll
        for (int ks = 0; ks < 4; ks++) {
            #pragma unroll
            for (int p = 0; p < 4; p++) {
                int n = p * 16 + krl;
                int ch = (2 * ks + kck) ^ (n & 7);
                uint32_t r0, r1, r2, r3;
                ldsm4(r0, r1, r2, r3, Kb + n * 128 + (ch << 4));
                mma16(sv[2 * p],     qa[ks][0], qa[ks][1], qa[ks][2], qa[ks][3], r0, r1);
                mma16(sv[2 * p + 1], qa[ks][0], qa[ks][1], qa[ks][2], qa[ks][3], r2, r3);
            }
        }

        // Causal mask (diagonal tile only)
        if (kt == qt) {
            const int r_lo = w * 16 + g, r_hi = r_lo + 8;
            #pragma unroll
            for (int nt = 0; nt < 8; nt++) {
                const int c0 = nt * 8 + 2 * t, c1 = c0 + 1;
                if (c0 > r_lo) sv[nt][0] = -1e30f;
                if (c1 > r_lo) sv[nt][1] = -1e30f;
                if (c0 > r_hi) sv[nt][2] = -1e30f;
                if (c1 > r_hi) sv[nt][3] = -1e30f;
            }
        }

        // Online softmax
        float mx0 = -1e30f, mx1 = -1e30f;
        #pragma unroll
        for (int nt = 0; nt < 8; nt++) {
            mx0 = fmaxf(mx0, fmaxf(sv[nt][0], sv[nt][1]));
            mx1 = fmaxf(mx1, fmaxf(sv[nt][2], sv[nt][3]));
        }
        mx0 = fmaxf(mx0, __shfl_xor_sync(0xffffffffu, mx0, 1));
        mx0 = fmaxf(mx0, __shfl_xor_sync(0xffffffffu, mx0, 2));
        mx1 = fmaxf(mx1, __shfl_xor_sync(0xffffffffu, mx1, 1));
        mx1 = fmaxf(mx1, __shfl_xor_sync(0xffffffffu, mx1, 2));

        const float mn0 = fmaxf(m0v, mx0), mn1 = fmaxf(m1v, mx1);
        const float al0 = __expf(m0v - mn0), al1 = __expf(m1v - mn1);
        m0v = mn0; m1v = mn1;

        float sum0 = 0.0f, sum1 = 0.0f;
        #pragma unroll
        for (int nt = 0; nt < 8; nt++) {
            sv[nt][0] = __expf(sv[nt][0] - mn0); sum0 += sv[nt][0];
            sv[nt][1] = __expf(sv[nt][1] - mn0); sum0 += sv[nt][1];
            sv[nt][2] = __expf(sv[nt][2] - mn1); sum1 += sv[nt][2];
            sv[nt][3] = __expf(sv[nt][3] - mn1); sum1 += sv[nt][3];
        }
        sum0 += __shfl_xor_sync(0xffffffffu, sum0, 1);
        sum0 += __shfl_xor_sync(0xffffffffu, sum0, 2);
        sum1 += __shfl_xor_sync(0xffffffffu, sum1, 1);
        sum1 += __shfl_xor_sync(0xffffffffu, sum1, 2);
        l0 = l0 * al0 + sum0;
        l1 = l1 * al1 + sum1;

        #pragma unroll
        for (int nt = 0; nt < 8; nt++) {
            o[nt][0] *= al0; o[nt][1] *= al0;
            o[nt][2] *= al1; o[nt][3] *= al1;
        }

        // O += P V  (P register-resident, packed to fp16)
        #pragma unroll
        for (int ks = 0; ks < 4; ks++) {
            const uint32_t p0 = packh2(sv[2 * ks][0],     sv[2 * ks][1]);
            const uint32_t p1 = packh2(sv[2 * ks][2],     sv[2 * ks][3]);
            const uint32_t p2 = packh2(sv[2 * ks + 1][0], sv[2 * ks + 1][1]);
            const uint32_t p3 = packh2(sv[2 * ks + 1][2], sv[2 * ks + 1][3]);
            #pragma unroll
            for (int p = 0; p < 4; p++) {
                int srow = ks * 16 + vrl;
                int ch = (2 * p + vck) ^ (srow & 7);
                uint32_t r0, r1, r2, r3;
                ldsm4t(r0, r1, r2, r3, Vb + srow * 128 + (ch << 4));
                mma16(o[2 * p],     p0, p1, p2, p3, r0, r1);
                mma16(o[2 * p + 1], p0, p1, p2, p3, r2, r3);
            }
        }
    }

    // Epilogue: normalize, write fp16 [T,B,E]
    const float inv0 = 1.0f / l0, inv1 = 1.0f / l1;
    __half* dlo = g_atth + ((size_t)(q0 + w * 16 + g) * Bb + b) * Ee + h * Dh;
    __half* dhi = dlo + (size_t)8 * Bb * Ee;
    #pragma unroll
    for (int nt = 0; nt < 8; nt++) {
        const int c = nt * 8 + 2 * t;
        *(uint32_t*)&dlo[c] = packh2(o[nt][0] * inv0, o[nt][1] * inv0);
        *(uint32_t*)&dhi[c] = packh2(o[nt][2] * inv1, o[nt][3] * inv1);
    }
}

// ---------------------------------------------------------------------------
// Launch
// ---------------------------------------------------------------------------
extern "C" void kernel_launch(void* const* d_in, const int* in_sizes, int n_in,
                              void* d_out, int out_size)
{
    const float* query = (const float*)d_in[0];
    const float* qkv_w = (const float*)d_in[1];
    const float* qkv_b = (const float*)d_in[2];
    const float* out_w = (const float*)d_in[3];
    const float* out_b = (const float*)d_in[4];
    float* out = (float*)d_out;

    void *p_xh = nullptr, *p_w1h = nullptr, *p_w2h = nullptr,
         *p_qkvh = nullptr, *p_atth = nullptr;
    cudaGetSymbolAddress(&p_xh,   g_xh);
    cudaGetSymbolAddress(&p_w1h,  g_w1h);
    cudaGetSymbolAddress(&p_w2h,  g_w2h);
    cudaGetSymbolAddress(&p_qkvh, g_qkvh);
    cudaGetSymbolAddress(&p_atth, g_atth);

    cudaFuncSetAttribute(gemm_f16, cudaFuncAttributeMaxDynamicSharedMemorySize, GSM);

    // 0) fp32 -> fp16 prepass
    cvt_f32_f16<<<(MROWS * Ee / 4 + 255) / 256, 256>>>((const float4*)query, (uint2*)p_xh,  MROWS * Ee / 4);
    cvt_f32_f16<<<(QKVF  * Ee / 4 + 255) / 256, 256>>>((const float4*)qkv_w, (uint2*)p_w1h, QKVF  * Ee / 4);
    cvt_f32_f16<<<(Ee    * Ee / 4 + 255) / 256, 256>>>((const float4*)out_w, (uint2*)p_w2h, Ee    * Ee / 4);

    // 1) QKV projection -> fp16, Q block scaled by 0.125
    gemm_f16<<<dim3(QKVF / BN, MROWS / BM), 128, GSM>>>(
        (const __half*)p_xh, (const __half*)p_w1h, qkv_b,
        (__half*)p_qkvh, nullptr, MROWS, QKVF, Ee, 1);

    // 2) Causal flash attention per (query-tile, b*H+h)
    flash_f16<<<dim3(Tt / 64, Bb * Hh), 128>>>();

    // 3) Output projection -> fp32 final output
    gemm_f16<<<dim3(Ee / BN, MROWS / BM), 128, GSM>>>(
        (const __half*)p_atth, (const __half*)p_w2h, out_b,
        nullptr, out, MROWS, Ee, Ee, 0);
}

// round 10
// speedup vs baseline: 1.0885x; 1.0099x over previous
#include <cuda_runtime.h>
#include <cuda_fp16.h>
#include <cstdint>

// Problem constants
#define Tt    1024
#define Bb    8
#define Ee    1024
#define Hh    16
#define Dh    64
#define QKVF  3072           // 3*E
#define MROWS 8192           // T*B

// Scratch (device globals — no runtime allocation allowed)
__device__ __half g_xh  [(size_t)MROWS * Ee];    // query, fp16
__device__ __half g_w1h [(size_t)QKVF * Ee];     // qkv_w, fp16
__device__ __half g_w2h [(size_t)Ee * Ee];       // out_w, fp16
__device__ __half g_qkvh[(size_t)MROWS * QKVF];  // qkv proj out (Q pre-scaled), fp16
__device__ __half g_atth[(size_t)MROWS * Ee];    // attention out, fp16

// ---------------------------------------------------------------------------
// Helpers
// ---------------------------------------------------------------------------
__device__ __forceinline__ uint32_t packh2(float lo, float hi) {
    __half2 h = __floats2half2_rn(lo, hi);
    return *reinterpret_cast<uint32_t*>(&h);
}

__device__ __forceinline__ void mma16(float* c,
                                      uint32_t a0, uint32_t a1, uint32_t a2, uint32_t a3,
                                      uint32_t b0, uint32_t b1) {
    asm volatile("mma.sync.aligned.m16n8k16.row.col.f32.f16.f16.f32 "
                 "{%0,%1,%2,%3}, {%4,%5,%6,%7}, {%8,%9}, {%0,%1,%2,%3};"
                 : "+f"(c[0]), "+f"(c[1]), "+f"(c[2]), "+f"(c[3])
                 : "r"(a0), "r"(a1), "r"(a2), "r"(a3), "r"(b0), "r"(b1));
}

__device__ __forceinline__ void ldsm4(uint32_t& r0, uint32_t& r1, uint32_t& r2, uint32_t& r3,
                                      uint32_t addr) {
    asm volatile("ldmatrix.sync.aligned.m8n8.x4.shared.b16 {%0,%1,%2,%3}, [%4];"
                 : "=r"(r0), "=r"(r1), "=r"(r2), "=r"(r3) : "r"(addr));
}

__device__ __forceinline__ void ldsm4t(uint32_t& r0, uint32_t& r1, uint32_t& r2, uint32_t& r3,
                                       uint32_t addr) {
    asm volatile("ldmatrix.sync.aligned.m8n8.x4.trans.shared.b16 {%0,%1,%2,%3}, [%4];"
                 : "=r"(r0), "=r"(r1), "=r"(r2), "=r"(r3) : "r"(addr));
}

// ---------------------------------------------------------------------------
// Prepass: fp32 -> fp16 (RN)
// ---------------------------------------------------------------------------
__global__ void cvt_f32_f16(const float4* __restrict__ in, uint2* __restrict__ out, int n4) {
    int i = blockIdx.x * blockDim.x + threadIdx.x;
    if (i < n4) {
        float4 v = in[i];
        uint2 o;
        o.x = packh2(v.x, v.y);
        o.y = packh2(v.z, v.w);
        out[i] = o;
    }
}

// ---------------------------------------------------------------------------
// fp16 tensor-core GEMM (NT) — proven R7 config.
// CTA 128x128, 4 warps (2m x 2n), warp tile 64x64, BK=32, 4-stage cp.async.
// ---------------------------------------------------------------------------
#define BM   128
#define BN   128
#define BKH  32
#define NSG  4
#define ABY  (BM * 64)          // 8192
#define BBY  (BN * 64)          // 8192
#define STG  (ABY + BBY)        // 16384
#define GSM  (NSG * STG)        // 65536

__global__ void __launch_bounds__(128, 2) gemm_f16(
    const __half* __restrict__ Ah, const __half* __restrict__ Bh,
    const float* __restrict__ bias, __half* __restrict__ Ch, float* __restrict__ Cf,
    int M, int N, int K, int qscale)
{
    extern __shared__ char smem[];
    const uint32_t sb = (uint32_t)__cvta_generic_to_shared(smem);
    const int tid  = threadIdx.x;
    const int lane = tid & 31;
    const int warp = tid >> 5;
    const int wm = warp & 1;
    const int wn = warp >> 1;
    const int m0 = blockIdx.y * BM;
    const int n0 = blockIdx.x * BN;

    float acc[4][8][4];
    #pragma unroll
    for (int mt = 0; mt < 4; mt++)
        #pragma unroll
        for (int nt = 0; nt < 8; nt++)
            #pragma unroll
            for (int i = 0; i < 4; i++) acc[mt][nt][i] = 0.0f;

    auto load_stage = [&](int s, int c) {
        const uint32_t base = sb + s * STG;
        const int k0 = c * BKH;
        #pragma unroll
        for (int i = 0; i < 8; i++) {
            int q = tid + i * 128;
            uint32_t dst;
            const __half* src;
            if (q < 512) {                   // A: 128 rows x 4 chunks
                int r = q >> 2, ch = q & 3;
                src = Ah + (size_t)(m0 + r) * K + k0 + ch * 8;
                dst = base + r * 64 + ((ch ^ ((r >> 1) & 3)) << 4);
            } else {                         // B: 128 rows x 4 chunks
                int q2 = q - 512;
                int r = q2 >> 2, ch = q2 & 3;
                src = Bh + (size_t)(n0 + r) * K + k0 + ch * 8;
                dst = base + ABY + r * 64 + ((ch ^ ((r >> 1) & 3)) << 4);
            }
            asm volatile("cp.async.cg.shared.global [%0], [%1], 16;" :: "r"(dst), "l"(src));
        }
        asm volatile("cp.async.commit_group;" ::: "memory");
    };

    const int nk = K / BKH;
    load_stage(0, 0);
    load_stage(1, 1);
    load_stage(2, 2);

    const int a_rl = ((lane >> 3) & 1) * 8 + (lane & 7);
    const int a_ck = lane >> 4;
    const int b_rl = ((lane >> 4) & 1) * 8 + (lane & 7);
    const int b_ck = (lane >> 3) & 1;

    uint32_t aoff[2][4], boff[2][4];
    #pragma unroll
    for (int ks = 0; ks < 2; ks++) {
        #pragma unroll
        for (int mt = 0; mt < 4; mt++) {
            int ar = wm * 64 + mt * 16 + a_rl;
            int ch = (2 * ks + a_ck) ^ ((ar >> 1) & 3);
            aoff[ks][mt] = ar * 64 + (ch << 4);
        }
        #pragma unroll
        for (int p = 0; p < 4; p++) {
            int br = wn * 64 + p * 16 + b_rl;
            int ch = (2 * ks + b_ck) ^ ((br >> 1) & 3);
            boff[ks][p] = ABY + br * 64 + (ch << 4);
        }
    }

    for (int c = 0; c < nk; c++) {
        const int s = c & (NSG - 1);
        if (c < nk - 1) asm volatile("cp.async.wait_group 2;" ::: "memory");
        else            asm volatile("cp.async.wait_group 0;" ::: "memory");
        __syncthreads();
        if (c + NSG - 1 < nk) load_stage((c + NSG - 1) & (NSG - 1), c + NSG - 1);

        const uint32_t base = sb + s * STG;
        #pragma unroll
        for (int ks = 0; ks < 2; ks++) {
            uint32_t af[4][4], bf[8][2];
            #pragma unroll
            for (int mt = 0; mt < 4; mt++)
                ldsm4(af[mt][0], af[mt][1], af[mt][2], af[mt][3], base + aoff[ks][mt]);
            #pragma unroll
            for (int p = 0; p < 4; p++) {
                uint32_t r0, r1, r2, r3;
                ldsm4(r0, r1, r2, r3, base + boff[ks][p]);
                bf[2 * p][0] = r0;     bf[2 * p][1] = r1;
                bf[2 * p + 1][0] = r2; bf[2 * p + 1][1] = r3;
            }
            #pragma unroll
            for (int mt = 0; mt < 4; mt++)
                #pragma unroll
                for (int nt = 0; nt < 8; nt++)
                    mma16(acc[mt][nt], af[mt][0], af[mt][1], af[mt][2], af[mt][3],
                          bf[nt][0], bf[nt][1]);
        }
    }

    // Epilogue
    const float scale = (qscale && n0 < Ee) ? 0.125f : 1.0f;
    const int g = lane >> 2, t = lane & 3;
    #pragma unroll
    for (int mt = 0; mt < 4; mt++) {
        const int r0 = m0 + wm * 64 + mt * 16 + g;
        #pragma unroll
        for (int nt = 0; nt < 8; nt++) {
            const int col = n0 + wn * 64 + nt * 8 + 2 * t;
            const float b0 = bias[col], b1 = bias[col + 1];
            float v00 = (acc[mt][nt][0] + b0) * scale;
            float v01 = (acc[mt][nt][1] + b1) * scale;
            float v10 = (acc[mt][nt][2] + b0) * scale;
            float v11 = (acc[mt][nt][3] + b1) * scale;
            if (Ch) {
                *(uint32_t*)&Ch[(size_t)r0 * N + col]       = packh2(v00, v01);
                *(uint32_t*)&Ch[(size_t)(r0 + 8) * N + col] = packh2(v10, v11);
            } else {
                *(float2*)&Cf[(size_t)r0 * N + col]       = make_float2(v00, v01);
                *(float2*)&Cf[(size_t)(r0 + 8) * N + col] = make_float2(v10, v11);
            }
        }
    }
}

// ---------------------------------------------------------------------------
// Flash attention, fp16 tensor cores, causal.
// NEW: q-tile 128 rows per block (4 warps; warp owns two 16-row strips).
// Each K/V ldsm fragment now feeds BOTH strips (mma/ldsm 2 -> 8), and K/V
// gmem tile traffic drops ~47%. kv tiles stay 64 rows, double-buffered.
// ---------------------------------------------------------------------------
#define FST 16384   // per-stage bytes: K 8KB + V 8KB
#define BQ  128

__global__ void __launch_bounds__(128, 2) flash_f16()
{
    __shared__ __align__(128) char fsm[2 * FST];
    const uint32_t sb = (uint32_t)__cvta_generic_to_shared(fsm);

    const int tid  = threadIdx.x;
    const int lane = tid & 31;
    const int g    = lane >> 2;
    const int t    = lane & 3;
    const int w    = tid >> 5;
    const int qt   = gridDim.x - 1 - blockIdx.x;   // heavy tiles first
    const int bh   = blockIdx.y;
    const int b    = bh >> 4;
    const int h    = bh & 15;
    const int q0   = qt * BQ;

    // Q fragments for 2 row-strips (Q pre-scaled by 0.125 in GEMM1 epilogue)
    uint32_t qa[2][4][4];
    #pragma unroll
    for (int r = 0; r < 2; r++) {
        const __half* qlo = g_qkvh + ((size_t)(q0 + w * 32 + r * 16 + g) * Bb + b) * QKVF + h * Dh;
        const __half* qhi = qlo + (size_t)8 * Bb * QKVF;
        #pragma unroll
        for (int ks = 0; ks < 4; ks++) {
            qa[r][ks][0] = *(const uint32_t*)(qlo + ks * 16 + 2 * t);
            qa[r][ks][1] = *(const uint32_t*)(qhi + ks * 16 + 2 * t);
            qa[r][ks][2] = *(const uint32_t*)(qlo + ks * 16 + 8 + 2 * t);
            qa[r][ks][3] = *(const uint32_t*)(qhi + ks * 16 + 8 + 2 * t);
        }
    }

    auto load_kv = [&](int st, int kt) {
        const uint32_t base = sb + st * FST;
        const int k0 = kt * 64;
        #pragma unroll
        for (int i = 0; i < 8; i++) {
            int q = tid + i * 128;
            int off, s, c;
            uint32_t dstb;
            if (q < 512) { s = q >> 3; c = q & 7; off = Ee;     dstb = base; }
            else { int q2 = q - 512; s = q2 >> 3; c = q2 & 7; off = 2 * Ee; dstb = base + 8192; }
            const __half* src = g_qkvh + ((size_t)(k0 + s) * Bb + b) * QKVF + off + h * Dh + c * 8;
            uint32_t dst = dstb + s * 128 + ((c ^ (s & 7)) << 4);
            asm volatile("cp.async.cg.shared.global [%0], [%1], 16;" :: "r"(dst), "l"(src));
        }
        asm volatile("cp.async.commit_group;" ::: "memory");
    };

    load_kv(0, 0);

    float o[2][8][4];
    #pragma unroll
    for (int r = 0; r < 2; r++)
        #pragma unroll
        for (int nt = 0; nt < 8; nt++)
            #pragma unroll
            for (int i = 0; i < 4; i++) o[r][nt][i] = 0.0f;
    float mrow[2][2] = {{-1e30f, -1e30f}, {-1e30f, -1e30f}};
    float lrow[2][2] = {{0.0f, 0.0f}, {0.0f, 0.0f}};

    const int krl = ((lane >> 4) & 1) * 8 + (lane & 7);
    const int kck = (lane >> 3) & 1;
    const int vrl = ((lane >> 3) & 1) * 8 + (lane & 7);
    const int vck = lane >> 4;

    const int nkt = 2 * qt + 2;
    for (int kt = 0; kt < nkt; kt++) {
        asm volatile("cp.async.wait_group 0;" ::: "memory");
        __syncthreads();
        if (kt + 1 < nkt) load_kv((kt + 1) & 1, kt + 1);

        const uint32_t Kb = sb + (kt & 1) * FST;
        const uint32_t Vb = Kb + 8192;

        // S = Q K^T for both strips (K fragments shared)
        float sv[2][8][4];
        #pragma unroll
        for (int r = 0; r < 2; r++)
            #pragma unroll
            for (int nt = 0; nt < 8; nt++)
                #pragma unroll
                for (int i = 0; i < 4; i++) sv[r][nt][i] = 0.0f;

        #pragma unroll
        for (int ks = 0; ks < 4; ks++) {
            #pragma unroll
            for (int p = 0; p < 4; p++) {
                int n = p * 16 + krl;
                int ch = (2 * ks + kck) ^ (n & 7);
                uint32_t r0, r1, r2, r3;
                ldsm4(r0, r1, r2, r3, Kb + n * 128 + (ch << 4));
                #pragma unroll
                for (int r = 0; r < 2; r++) {
                    mma16(sv[r][2 * p],     qa[r][ks][0], qa[r][ks][1], qa[r][ks][2], qa[r][ks][3], r0, r1);
                    mma16(sv[r][2 * p + 1], qa[r][ks][0], qa[r][ks][1], qa[r][ks][2], qa[r][ks][3], r2, r3);
                }
            }
        }

        // Causal mask: needed only for the last two kv tiles of this q-tile
        if (kt >= 2 * qt) {
            const int k0c = kt * 64;
            #pragma unroll
            for (int r = 0; r < 2; r++) {
                const int row_lo = q0 + w * 32 + r * 16 + g;
                const int row_hi = row_lo + 8;
                #pragma unroll
                for (int nt = 0; nt < 8; nt++) {
                    const int c0 = k0c + nt * 8 + 2 * t, c1 = c0 + 1;
                    if (c0 > row_lo) sv[r][nt][0] = -1e30f;
                    if (c1 > row_lo) sv[r][nt][1] = -1e30f;
                    if (c0 > row_hi) sv[r][nt][2] = -1e30f;
                    if (c1 > row_hi) sv[r][nt][3] = -1e30f;
                }
            }
        }

        // Online softmax per strip
        #pragma unroll
        for (int r = 0; r < 2; r++) {
            float mx0 = -1e30f, mx1 = -1e30f;
            #pragma unroll
            for (int nt = 0; nt < 8; nt++) {
                mx0 = fmaxf(mx0, fmaxf(sv[r][nt][0], sv[r][nt][1]));
                mx1 = fmaxf(mx1, fmaxf(sv[r][nt][2], sv[r][nt][3]));
            }
            mx0 = fmaxf(mx0, __shfl_xor_sync(0xffffffffu, mx0, 1));
            mx0 = fmaxf(mx0, __shfl_xor_sync(0xffffffffu, mx0, 2));
            mx1 = fmaxf(mx1, __shfl_xor_sync(0xffffffffu, mx1, 1));
            mx1 = fmaxf(mx1, __shfl_xor_sync(0xffffffffu, mx1, 2));

            const float mn0 = fmaxf(mrow[r][0], mx0), mn1 = fmaxf(mrow[r][1], mx1);
            const float al0 = __expf(mrow[r][0] - mn0), al1 = __expf(mrow[r][1] - mn1);
            mrow[r][0] = mn0; mrow[r][1] = mn1;

            float sum0 = 0.0f, sum1 = 0.0f;
            #pragma unroll
            for (int nt = 0; nt < 8; nt++) {
                sv[r][nt][0] = __expf(sv[r][nt][0] - mn0); sum0 += sv[r][nt][0];
                sv[r][nt][1] = __expf(sv[r][nt][1] - mn0); sum0 += sv[r][nt][1];
                sv[r][nt][2] = __expf(sv[r][nt][2] - mn1); sum1 += sv[r][nt][2];
                sv[r][nt][3] = __expf(sv[r][nt][3] - mn1); sum1 += sv[r][nt][3];
            }
            sum0 += __shfl_xor_sync(0xffffffffu, sum0, 1);
            sum0 += __shfl_xor_sync(0xffffffffu, sum0, 2);
            sum1 += __shfl_xor_sync(0xffffffffu, sum1, 1);
            sum1 += __shfl_xor_sync(0xffffffffu, sum1, 2);
            lrow[r][0] = lrow[r][0] * al0 + sum0;
            lrow[r][1] = lrow[r][1] * al1 + sum1;

            #pragma unroll
            for (int nt = 0; nt < 8; nt++) {
                o[r][nt][0] *= al0; o[r][nt][1] *= al0;
                o[r][nt][2] *= al1; o[r][nt][3] *= al1;
            }
        }

        // Pack P fragments (register-resident)
        uint32_t pp[2][4][4];
        #pragma unroll
        for (int r = 0; r < 2; r++)
            #pragma unroll
            for (int ks = 0; ks < 4; ks++) {
                pp[r][ks][0] = packh2(sv[r][2 * ks][0],     sv[r][2 * ks][1]);
                pp[r][ks][1] = packh2(sv[r][2 * ks][2],     sv[r][2 * ks][3]);
                pp[r][ks][2] = packh2(sv[r][2 * ks + 1][0], sv[r][2 * ks + 1][1]);
                pp[r][ks][3] = packh2(sv[r][2 * ks + 1][2], sv[r][2 * ks + 1][3]);
            }

        // O += P V (V fragments shared across strips)
        #pragma unroll
        for (int ks = 0; ks < 4; ks++) {
            #pragma unroll
            for (int p = 0; p < 4; p++) {
                int srow = ks * 16 + vrl;
                int ch = (2 * p + vck) ^ (srow & 7);
                uint32_t r0, r1, r2, r3;
                ldsm4t(r0, r1, r2, r3, Vb + srow * 128 + (ch << 4));
                #pragma unroll
                for (int r = 0; r < 2; r++) {
                    mma16(o[r][2 * p],     pp[r][ks][0], pp[r][ks][1], pp[r][ks][2], pp[r][ks][3], r0, r1);
                    mma16(o[r][2 * p + 1], pp[r][ks][0], pp[r][ks][1], pp[r][ks][2], pp[r][ks][3], r2, r3);
                }
            }
        }
    }

    // Epilogue: normalize, write fp16 [T,B,E]
    #pragma unroll
    for (int r = 0; r < 2; r++) {
        const float inv0 = 1.0f / lrow[r][0], inv1 = 1.0f / lrow[r][1];
        __half* dlo = g_atth + ((size_t)(q0 + w * 32 + r * 16 + g) * Bb + b) * Ee + h * Dh;
        __half* dhi = dlo + (size_t)8 * Bb * Ee;
        #pragma unroll
        for (int nt = 0; nt < 8; nt++) {
            const int c = nt * 8 + 2 * t;
            *(uint32_t*)&dlo[c] = packh2(o[r][nt][0] * inv0, o[r][nt][1] * inv0);
            *(uint32_t*)&dhi[c] = packh2(o[r][nt][2] * inv1, o[r][nt][3] * inv1);
        }
    }
}

// ---------------------------------------------------------------------------
// Launch
// ---------------------------------------------------------------------------
extern "C" void kernel_launch(void* const* d_in, const int* in_sizes, int n_in,
                              void* d_out, int out_size)
{
    const float* query = (const float*)d_in[0];
    const float* qkv_w = (const float*)d_in[1];
    const float* qkv_b = (const float*)d_in[2];
    const float* out_w = (const float*)d_in[3];
    const float* out_b = (const float*)d_in[4];
    float* out = (float*)d_out;

    void *p_xh = nullptr, *p_w1h = nullptr, *p_w2h = nullptr,
         *p_qkvh = nullptr, *p_atth = nullptr;
    cudaGetSymbolAddress(&p_xh,   g_xh);
    cudaGetSymbolAddress(&p_w1h,  g_w1h);
    cudaGetSymbolAddress(&p_w2h,  g_w2h);
    cudaGetSymbolAddress(&p_qkvh, g_qkvh);
    cudaGetSymbolAddress(&p_atth, g_atth);

    cudaFuncSetAttribute(gemm_f16, cudaFuncAttributeMaxDynamicSharedMemorySize, GSM);

    // 0) fp32 -> fp16 prepass
    cvt_f32_f16<<<(MROWS * Ee / 4 + 255) / 256, 256>>>((const float4*)query, (uint2*)p_xh,  MROWS * Ee / 4);
    cvt_f32_f16<<<(QKVF  * Ee / 4 + 255) / 256, 256>>>((const float4*)qkv_w, (uint2*)p_w1h, QKVF  * Ee / 4);
    cvt_f32_f16<<<(Ee    * Ee / 4 + 255) / 256, 256>>>((const float4*)out_w, (uint2*)p_w2h, Ee    * Ee / 4);

    // 1) QKV projection -> fp16, Q block scaled by 0.125
    gemm_f16<<<dim3(QKVF / BN, MROWS / BM), 128, GSM>>>(
        (const __half*)p_xh, (const __half*)p_w1h, qkv_b,
        (__half*)p_qkvh, nullptr, MROWS, QKVF, Ee, 1);

    // 2) Causal flash attention per (128-row query tile, b*H+h)
    flash_f16<<<dim3(Tt / BQ, Bb * Hh), 128>>>();

    // 3) Output projection -> fp32 final output
    gemm_f16<<<dim3(Ee / BN, MROWS / BM), 128, GSM>>>(
        (const __half*)p_atth, (const __half*)p_w2h, out_b,
        nullptr, out, MROWS, Ee, Ee, 0);
}